// round 2
// baseline (speedup 1.0000x reference)
#include <cuda_runtime.h>
#include <math.h>

#define OUTW  50
#define AANCH 9
#define NANCH 22500          // 50*50*9
#define BATCH 16
#define MGT   16
#define NFEAT 512
#define NOUT  45             // 9 cls + 36 box
#define NOUTP 48             // padded for float4
#define KCOLS 4608           // 512 * 9
#define CBLK  16

// ---------------- scratch (device globals; no allocation) ----------------
__device__ float g_weff[KCOLS * NOUTP];               // [(c*9+t)*48 + o]
__device__ float g_beff[NOUTP];
__device__ float g_logits[BATCH * NANCH];
__device__ float g_pred[(size_t)BATCH * NANCH * 4];
__device__ float g_iou[(size_t)BATCH * NANCH * MGT];  // [(b*N+n)*16+m]
__device__ float g_maxg[BATCH * MGT];
__device__ float g_sums[8];  // 0:n_pos 1:reg_sum 2:pos_sum 3:n_neg 4:neg_sum

// ---------------- helpers ----------------
__device__ __forceinline__ void anchor_box(int h, int w, int a,
                                           float& x1, float& y1, float& x2, float& y2) {
    const float SC[3] = {2.f, 4.f, 6.f};
    const float RT[3] = {0.5f, 1.f, 1.5f};
    float s = SC[a % 3], r = RT[a / 3];
    float hw = s * r * 0.5f;   // half width
    float hh = s * 0.5f;       // half height
    float cx = (float)h + 0.5f;   // NOTE: cx follows the H index (ref's reshape)
    float cy = (float)w + 0.5f;
    x1 = fminf(fmaxf(cx - hw, 0.f), 50.f);
    x2 = fminf(fmaxf(cx + hw, 0.f), 50.f);
    y1 = fminf(fmaxf(cy - hh, 0.f), 50.f);
    y2 = fminf(fmaxf(cy + hh, 0.f), 50.f);
}

__device__ __forceinline__ float softplusf(float x) {
    return fmaxf(x, 0.f) + log1pf(expf(-fabsf(x)));
}
__device__ __forceinline__ float sl1(float d) {
    float ad = fabsf(d);
    return ad < 1.f ? 0.5f * d * d : ad - 0.5f;
}

// ---------------- 1. init ----------------
__global__ void init_kernel() {
    int i = blockIdx.x * 256 + threadIdx.x;
    if (i < KCOLS * NOUTP) g_weff[i] = 0.f;
    if (i < BATCH * MGT)   g_maxg[i] = 0.f;
    if (i < 8)             g_sums[i] = 0.f;
}

// ---------------- 2. compose w_eff = proj @ w1 ----------------
// grid (36 col-tiles of 128, 8 c'-chunks of 64), 128 threads
#define CPCHUNK 64
__global__ __launch_bounds__(128) void compose_kernel(const float* __restrict__ w1,
                                                      const float* __restrict__ wcls,
                                                      const float* __restrict__ wbox) {
    __shared__ __align__(16) float projT[CPCHUNK][NOUTP];
    int cp0 = blockIdx.y * CPCHUNK;
    for (int i = threadIdx.x; i < CPCHUNK * NOUTP; i += 128) {
        int cp = i / NOUTP, o = i % NOUTP;
        float v = 0.f;
        if (o < 9)       v = wcls[o * NFEAT + cp0 + cp];
        else if (o < 45) v = wbox[(o - 9) * NFEAT + cp0 + cp];
        projT[cp][o] = v;
    }
    __syncthreads();
    int col = blockIdx.x * 128 + threadIdx.x;  // col = c*9 + t, < 4608
    float acc[NOUTP];
#pragma unroll
    for (int o = 0; o < NOUTP; o++) acc[o] = 0.f;
#pragma unroll 4
    for (int cp = 0; cp < CPCHUNK; cp++) {
        float wv = w1[(size_t)(cp0 + cp) * KCOLS + col];
#pragma unroll
        for (int og = 0; og < 12; og++) {
            float4 pv = *(const float4*)&projT[cp][og * 4];
            acc[og * 4 + 0] += pv.x * wv;
            acc[og * 4 + 1] += pv.y * wv;
            acc[og * 4 + 2] += pv.z * wv;
            acc[og * 4 + 3] += pv.w * wv;
        }
    }
    float* dst = &g_weff[(size_t)col * NOUTP];
#pragma unroll
    for (int o = 0; o < NOUTP; o++) atomicAdd(&dst[o], acc[o]);
}

// ---------------- 3. b_eff ----------------
__global__ void beff_kernel(const float* __restrict__ b1, const float* __restrict__ wcls,
                            const float* __restrict__ bcls, const float* __restrict__ wbox,
                            const float* __restrict__ bbox) {
    int o = threadIdx.x;
    if (o >= NOUTP) return;
    if (o >= NOUT) { g_beff[o] = 0.f; return; }
    float s = (o < 9) ? bcls[o] : bbox[o - 9];
    const float* pr = (o < 9) ? &wcls[o * NFEAT] : &wbox[(o - 9) * NFEAT];
#pragma unroll 8
    for (int c = 0; c < NFEAT; c++) s += pr[c] * b1[c];
    g_beff[o] = s;
}

// ---------------- 4. conv (45-out-channel 3x3, fused heads) ----------------
// grid (20 pixel-tiles of 128, 16 batches), 128 threads
__global__ __launch_bounds__(128) void conv_kernel(const float* __restrict__ feat,
                                                   float* __restrict__ out) {
    int tile = blockIdx.x, b = blockIdx.y;
    int p = tile * 128 + threadIdx.x;
    bool act = p < OUTW * OUTW;
    int pc = act ? p : (OUTW * OUTW - 1);
    int h = pc / OUTW, w = pc % OUTW;
    int hfirst = (tile * 128) / OUTW;
    int hbase = hfirst - 1;
    int pr0 = h - hfirst;  // 0..3

    __shared__ __align__(16) float wsh[CBLK * 9 * NOUTP];  // 27648 B
    __shared__ float psh[CBLK][6][52];                     // 19968 B

    float acc[NOUT];
#pragma unroll
    for (int i = 0; i < NOUT; i++) acc[i] = 0.f;

#pragma unroll 1
    for (int c0 = 0; c0 < NFEAT; c0 += CBLK) {
        const float* wg = &g_weff[(size_t)c0 * 9 * NOUTP];
        for (int i = threadIdx.x; i < CBLK * 9 * NOUTP; i += 128) wsh[i] = wg[i];
        for (int i = threadIdx.x; i < CBLK * 6 * 52; i += 128) {
            int ci = i / (6 * 52);
            int rem = i % (6 * 52);
            int row = rem / 52, col = rem % 52;
            int hh = hbase + row, ww = col - 1;
            float v = 0.f;
            if (hh >= 0 && hh < OUTW && ww >= 0 && ww < OUTW)
                v = feat[(((size_t)b * NFEAT + c0 + ci) * OUTW + hh) * OUTW + ww];
            psh[ci][row][col] = v;
        }
        __syncthreads();
#pragma unroll 1
        for (int ci = 0; ci < CBLK; ci++) {
            float f[9];
#pragma unroll
            for (int ky = 0; ky < 3; ky++)
#pragma unroll
                for (int kx = 0; kx < 3; kx++)
                    f[ky * 3 + kx] = psh[ci][pr0 + ky][w + kx];
            const float* wr = &wsh[ci * 9 * NOUTP];
#pragma unroll
            for (int t = 0; t < 9; t++) {
                float fv = f[t];
#pragma unroll
                for (int og = 0; og < 11; og++) {
                    float4 wv = *(const float4*)&wr[t * NOUTP + og * 4];
                    acc[og * 4 + 0] += fv * wv.x;
                    acc[og * 4 + 1] += fv * wv.y;
                    acc[og * 4 + 2] += fv * wv.z;
                    acc[og * 4 + 3] += fv * wv.w;
                }
                acc[44] += fv * wr[t * NOUTP + 44];
            }
        }
        __syncthreads();
    }

    if (act) {
        int n = h * (OUTW * AANCH) + w * AANCH;
        size_t bn = (size_t)b * NANCH;
#pragma unroll
        for (int a = 0; a < AANCH; a++) g_logits[bn + n + a] = acc[a] + g_beff[a];
#pragma unroll
        for (int a = 0; a < AANCH; a++) {
            float o0 = acc[9 + a * 4 + 0] + g_beff[9 + a * 4 + 0];
            float o1 = acc[9 + a * 4 + 1] + g_beff[9 + a * 4 + 1];
            float o2 = acc[9 + a * 4 + 2] + g_beff[9 + a * 4 + 2];
            float o3 = acc[9 + a * 4 + 3] + g_beff[9 + a * 4 + 3];
            size_t base = (bn + n + a) * 4;
            g_pred[base + 0] = o0; g_pred[base + 1] = o1;
            g_pred[base + 2] = o2; g_pred[base + 3] = o3;
            float x1, y1, x2, y2;
            anchor_box(h, w, a, x1, y1, x2, y2);
            float acx = (x1 + x2) * 0.5f, acy = (y1 + y2) * 0.5f;
            float aw = fmaxf(x2 - x1, 1e-6f), ah = fmaxf(y2 - y1, 1e-6f);
            float pcx = acx + o0 * aw, pcy = acy + o1 * ah;
            float pw = aw * expf(o2), ph = ah * expf(o3);
            out[1 + base + 0] = pcx - pw * 0.5f;
            out[1 + base + 1] = pcy - ph * 0.5f;
            out[1 + base + 2] = pcx + pw * 0.5f;
            out[1 + base + 3] = pcy + ph * 0.5f;
        }
    }
}

// ---------------- 5. IoU + per-gt max ----------------
// grid (88, 16), 256 threads
__global__ void iou_kernel(const float* __restrict__ gt) {
    int b = blockIdx.y;
    int n = blockIdx.x * 256 + threadIdx.x;
    __shared__ float gx1[MGT], gy1[MGT], gx2[MGT], gy2[MGT];
    if (threadIdx.x < MGT) {
        int m = threadIdx.x;
        gx1[m] = gt[(b * MGT + m) * 4 + 0] * (1.f / 16.f);
        gy1[m] = gt[(b * MGT + m) * 4 + 1] * (1.f / 16.f);
        gx2[m] = gt[(b * MGT + m) * 4 + 2] * (1.f / 16.f);
        gy2[m] = gt[(b * MGT + m) * 4 + 3] * (1.f / 16.f);
    }
    __syncthreads();
    float lmax[MGT];
#pragma unroll
    for (int m = 0; m < MGT; m++) lmax[m] = 0.f;
    if (n < NANCH) {
        int h = n / (OUTW * AANCH);
        int rem = n % (OUTW * AANCH);
        int w = rem / AANCH, a = rem % AANCH;
        float x1, y1, x2, y2;
        anchor_box(h, w, a, x1, y1, x2, y2);
        float area_a = (x2 - x1) * (y2 - y1);
        size_t base = ((size_t)b * NANCH + n) * MGT;
#pragma unroll
        for (int m = 0; m < MGT; m++) {
            float ix1 = fmaxf(x1, gx1[m]), iy1 = fmaxf(y1, gy1[m]);
            float ix2 = fminf(x2, gx2[m]), iy2 = fminf(y2, gy2[m]);
            float inter = fmaxf(ix2 - ix1, 0.f) * fmaxf(iy2 - iy1, 0.f);
            float area_g = (gx2[m] - gx1[m]) * (gy2[m] - gy1[m]);
            float iou = inter / (area_a + area_g - inter + 1e-8f);
            g_iou[base + m] = iou;
            lmax[m] = iou;
        }
    }
#pragma unroll
    for (int m = 0; m < MGT; m++) {
#pragma unroll
        for (int s = 16; s; s >>= 1)
            lmax[m] = fmaxf(lmax[m], __shfl_xor_sync(0xffffffffu, lmax[m], s));
    }
    if ((threadIdx.x & 31) == 0) {
#pragma unroll
        for (int m = 0; m < MGT; m++)
            atomicMax((int*)&g_maxg[b * MGT + m], __float_as_int(lmax[m]));  // iou >= 0
    }
}

// ---------------- 6. loss accumulation ----------------
__global__ void loss_kernel(const float* __restrict__ gt) {
    int b = blockIdx.y;
    int n = blockIdx.x * 256 + threadIdx.x;
    __shared__ float gcx[MGT], gcy[MGT], gww[MGT], ghh[MGT], gmax[MGT];
    if (threadIdx.x < MGT) {
        int m = threadIdx.x;
        float x1 = gt[(b * MGT + m) * 4 + 0] * (1.f / 16.f);
        float y1 = gt[(b * MGT + m) * 4 + 1] * (1.f / 16.f);
        float x2 = gt[(b * MGT + m) * 4 + 2] * (1.f / 16.f);
        float y2 = gt[(b * MGT + m) * 4 + 3] * (1.f / 16.f);
        gcx[m] = (x1 + x2) * 0.5f;
        gcy[m] = (y1 + y2) * 0.5f;
        gww[m] = fmaxf(x2 - x1, 1e-6f);
        ghh[m] = fmaxf(y2 - y1, 1e-6f);
        gmax[m] = g_maxg[b * MGT + m];
    }
    __syncthreads();
    float cnt = 0.f, reg = 0.f, pls = 0.f, negcnt = 0.f, negls = 0.f;
    if (n < NANCH) {
        int h = n / (OUTW * AANCH);
        int rem = n % (OUTW * AANCH);
        int w = rem / AANCH, a = rem % AANCH;
        float x1, y1, x2, y2;
        anchor_box(h, w, a, x1, y1, x2, y2);
        float acx = (x1 + x2) * 0.5f, acy = (y1 + y2) * 0.5f;
        float aw = fmaxf(x2 - x1, 1e-6f), ah = fmaxf(y2 - y1, 1e-6f);
        float logit = g_logits[(size_t)b * NANCH + n];
        float sp_neg = softplusf(-logit);
        const float* pr = &g_pred[((size_t)b * NANCH + n) * 4];
        float p0 = pr[0], p1 = pr[1], p2 = pr[2], p3 = pr[3];
        size_t base = ((size_t)b * NANCH + n) * MGT;
        bool allneg = true;
#pragma unroll
        for (int m = 0; m < MGT; m++) {
            float iou = g_iou[base + m];
            bool pos = ((iou == gmax[m]) && (gmax[m] > 0.f)) || (iou > 0.7f);
            if (iou >= 0.3f) allneg = false;
            if (pos) {
                cnt += 1.f;
                float tx = (gcx[m] - acx) / aw;
                float ty = (gcy[m] - acy) / ah;
                float tw = logf(gww[m] / aw);
                float th = logf(ghh[m] / ah);
                reg += sl1(tx - p0) + sl1(ty - p1) + sl1(tw - p2) + sl1(th - p3);
                pls += sp_neg;
            }
        }
        if (allneg) { negcnt = 1.f; negls = softplusf(logit); }
    }
#pragma unroll
    for (int s = 16; s; s >>= 1) {
        cnt    += __shfl_xor_sync(0xffffffffu, cnt, s);
        reg    += __shfl_xor_sync(0xffffffffu, reg, s);
        pls    += __shfl_xor_sync(0xffffffffu, pls, s);
        negcnt += __shfl_xor_sync(0xffffffffu, negcnt, s);
        negls  += __shfl_xor_sync(0xffffffffu, negls, s);
    }
    if ((threadIdx.x & 31) == 0) {
        atomicAdd(&g_sums[0], cnt);
        atomicAdd(&g_sums[1], reg);
        atomicAdd(&g_sums[2], pls);
        atomicAdd(&g_sums[3], negcnt);
        atomicAdd(&g_sums[4], negls);
    }
}

// ---------------- 7. finalize ----------------
__global__ void fin_kernel(float* __restrict__ out) {
    float npos = fmaxf(g_sums[0], 1.f);
    float nneg = fmaxf(g_sums[3], 1.f);
    float reg_loss = g_sums[1] / (4.f * npos);
    float pos_loss = g_sums[2] / npos;
    float neg_loss = g_sums[4] / nneg;
    out[0] = 0.5f * (pos_loss + neg_loss) + 5.f * reg_loss;  // W_CONF=1, W_REG=5
}

// ---------------- launch ----------------
extern "C" void kernel_launch(void* const* d_in, const int* in_sizes, int n_in,
                              void* d_out, int out_size) {
    const float* feat = (const float*)d_in[0];
    const float* gt   = (const float*)d_in[1];
    const float* w1   = (const float*)d_in[2];
    const float* b1   = (const float*)d_in[3];
    const float* wcls = (const float*)d_in[4];
    const float* bcls = (const float*)d_in[5];
    const float* wbox = (const float*)d_in[6];
    const float* bbox = (const float*)d_in[7];
    float* out = (float*)d_out;

    init_kernel<<<(KCOLS * NOUTP + 255) / 256, 256>>>();
    compose_kernel<<<dim3(KCOLS / 128, NFEAT / CPCHUNK), 128>>>(w1, wcls, wbox);
    beff_kernel<<<1, 64>>>(b1, wcls, bcls, wbox, bbox);
    conv_kernel<<<dim3(20, BATCH), 128>>>(feat, out);
    iou_kernel<<<dim3((NANCH + 255) / 256, BATCH), 256>>>(gt);
    loss_kernel<<<dim3((NANCH + 255) / 256, BATCH), 256>>>(gt);
    fin_kernel<<<1, 1>>>(out);
}

// round 5
// speedup vs baseline: 1.3309x; 1.3309x over previous
#include <cuda_runtime.h>
#include <cuda_bf16.h>
#include <math.h>
#include <stdint.h>

#define OUTW  50
#define AANCH 9
#define NANCH 22500
#define BATCH 16
#define MGT   16
#define NFEAT 512
#define NOUT  45
#define NOUTP 48
#define KCOLS 4608
#define PADW  52
#define PPB   2704            // 52*52
#define MROWS 43264           // 16*2704
#define GUARD 64
#define AROWS (MROWS + 2*GUARD)
#define MTILE 128
#define NTILES 338            // 43264/128
#define TAPS  9
#define CHUNKS 72             // 9 taps * 8 ch-chunks of 64

// smem stage layout (bf16, row stride 72 elems = 144B -> conflict-free ldmatrix)
#define ASTR  72
#define A_LO  18432           // 128*72*2
#define B_HI  36864
#define B_LO  46080           // +64*72*2
#define STAGE 55296
#define SMEM_TOTAL (2*STAGE)  // 110592

// ---------------- scratch ----------------
__device__ float g_weff[KCOLS * NOUTP];
__device__ float g_beff[NOUTP];
__device__ float g_logits[BATCH * NANCH];
__device__ float g_pred[(size_t)BATCH * NANCH * 4];
__device__ float g_iou[(size_t)BATCH * NANCH * MGT];
__device__ float g_maxg[BATCH * MGT];
__device__ float g_sums[8];
__device__ __nv_bfloat16 g_Ahi[(size_t)AROWS * NFEAT];   // zero .bss: border/guard stay 0
__device__ __nv_bfloat16 g_Alo[(size_t)AROWS * NFEAT];
__device__ __nv_bfloat16 g_Bhi[TAPS * 64 * NFEAT];       // rows 45..63 stay 0
__device__ __nv_bfloat16 g_Blo[TAPS * 64 * NFEAT];

// ---------------- ptx helpers (baseline sm_80+ only) ----------------
__device__ __forceinline__ uint32_t smem_u32(const void* p) {
    uint32_t a;
    asm("{ .reg .u64 t; cvta.to.shared.u64 t, %1; cvt.u32.u64 %0, t; }" : "=r"(a) : "l"(p));
    return a;
}
__device__ __forceinline__ void cpa16(uint32_t dst, const void* src) {
    unsigned long long g = (unsigned long long)__cvta_generic_to_global(src);
    asm volatile("cp.async.cg.shared.global [%0], [%1], 16;" :: "r"(dst), "l"(g) : "memory");
}
#define CP_COMMIT() asm volatile("cp.async.commit_group;" ::: "memory")
#define CP_WAIT1()  asm volatile("cp.async.wait_group 1;" ::: "memory")
#define CP_WAIT0()  asm volatile("cp.async.wait_group 0;" ::: "memory")

__device__ __forceinline__ void ldm4(uint32_t* r, uint32_t addr) {
    asm volatile("ldmatrix.sync.aligned.m8n8.x4.shared.b16 {%0,%1,%2,%3}, [%4];"
                 : "=r"(r[0]), "=r"(r[1]), "=r"(r[2]), "=r"(r[3]) : "r"(addr));
}
__device__ __forceinline__ void mma16816(float* d, const uint32_t* a, uint32_t b0, uint32_t b1) {
    asm volatile("mma.sync.aligned.m16n8k16.row.col.f32.bf16.bf16.f32 "
                 "{%0,%1,%2,%3},{%4,%5,%6,%7},{%8,%9},{%0,%1,%2,%3};"
                 : "+f"(d[0]), "+f"(d[1]), "+f"(d[2]), "+f"(d[3])
                 : "r"(a[0]), "r"(a[1]), "r"(a[2]), "r"(a[3]), "r"(b0), "r"(b1));
}

// ---------------- math helpers ----------------
__device__ __forceinline__ void anchor_box(int h, int w, int a,
                                           float& x1, float& y1, float& x2, float& y2) {
    const float SC[3] = {2.f, 4.f, 6.f};
    const float RT[3] = {0.5f, 1.f, 1.5f};
    float s = SC[a % 3], r = RT[a / 3];
    float hw = s * r * 0.5f, hh = s * 0.5f;
    float cx = (float)h + 0.5f, cy = (float)w + 0.5f;
    x1 = fminf(fmaxf(cx - hw, 0.f), 50.f);
    x2 = fminf(fmaxf(cx + hw, 0.f), 50.f);
    y1 = fminf(fmaxf(cy - hh, 0.f), 50.f);
    y2 = fminf(fmaxf(cy + hh, 0.f), 50.f);
}
__device__ __forceinline__ float softplusf(float x) {
    return fmaxf(x, 0.f) + log1pf(expf(-fabsf(x)));
}
__device__ __forceinline__ float sl1(float d) {
    float ad = fabsf(d);
    return ad < 1.f ? 0.5f * d * d : ad - 0.5f;
}

// ---------------- 1. init ----------------
__global__ void init_kernel() {
    int i = blockIdx.x * 256 + threadIdx.x;
    if (i < KCOLS * NOUTP) g_weff[i] = 0.f;
    if (i < BATCH * MGT)   g_maxg[i] = 0.f;
    if (i < 8)             g_sums[i] = 0.f;
}

// ---------------- 2. compose w_eff = proj @ w1 ----------------
#define CPCHUNK 64
__global__ __launch_bounds__(128) void compose_kernel(const float* __restrict__ w1,
                                                      const float* __restrict__ wcls,
                                                      const float* __restrict__ wbox) {
    __shared__ __align__(16) float projT[CPCHUNK][NOUTP];
    int cp0 = blockIdx.y * CPCHUNK;
    for (int i = threadIdx.x; i < CPCHUNK * NOUTP; i += 128) {
        int cp = i / NOUTP, o = i % NOUTP;
        float v = 0.f;
        if (o < 9)       v = wcls[o * NFEAT + cp0 + cp];
        else if (o < 45) v = wbox[(o - 9) * NFEAT + cp0 + cp];
        projT[cp][o] = v;
    }
    __syncthreads();
    int col = blockIdx.x * 128 + threadIdx.x;
    float acc[NOUTP];
#pragma unroll
    for (int o = 0; o < NOUTP; o++) acc[o] = 0.f;
#pragma unroll 4
    for (int cp = 0; cp < CPCHUNK; cp++) {
        float wv = w1[(size_t)(cp0 + cp) * KCOLS + col];
#pragma unroll
        for (int og = 0; og < 12; og++) {
            float4 pv = *(const float4*)&projT[cp][og * 4];
            acc[og * 4 + 0] += pv.x * wv;
            acc[og * 4 + 1] += pv.y * wv;
            acc[og * 4 + 2] += pv.z * wv;
            acc[og * 4 + 3] += pv.w * wv;
        }
    }
    float* dst = &g_weff[(size_t)col * NOUTP];
#pragma unroll
    for (int o = 0; o < NOUTP; o++) atomicAdd(&dst[o], acc[o]);
}

// ---------------- 3. b_eff ----------------
__global__ void beff_kernel(const float* __restrict__ b1, const float* __restrict__ wcls,
                            const float* __restrict__ bcls, const float* __restrict__ wbox,
                            const float* __restrict__ bbox) {
    int o = threadIdx.x;
    if (o >= NOUTP) return;
    if (o >= NOUT) { g_beff[o] = 0.f; return; }
    float s = (o < 9) ? bcls[o] : bbox[o - 9];
    const float* pr = (o < 9) ? &wcls[o * NFEAT] : &wbox[(o - 9) * NFEAT];
#pragma unroll 8
    for (int c = 0; c < NFEAT; c++) s += pr[c] * b1[c];
    g_beff[o] = s;
}

// ---------------- 4. transpose + bf16 split ----------------
__global__ __launch_bounds__(256) void transpose_kernel(const float* __restrict__ feat) {
    __shared__ float t[64][51];
    int h = blockIdx.x, b = blockIdx.y, c0 = blockIdx.z * 64;
    for (int i = threadIdx.x; i < 64 * 50; i += 256) {
        int c = i / 50, w = i % 50;
        t[c][w] = feat[(((size_t)b * NFEAT + c0 + c) * OUTW + h) * OUTW + w];
    }
    __syncthreads();
    for (int j = threadIdx.x; j < 64 * 50; j += 256) {
        int w = j >> 6, c = j & 63;
        float a = t[c][w];
        __nv_bfloat16 hi = __float2bfloat16(a);
        float res = a - __bfloat162float(hi);
        size_t idx = ((size_t)(b * PPB + (h + 1) * PADW + (w + 1) + GUARD)) * NFEAT + c0 + c;
        g_Ahi[idx] = hi;
        g_Alo[idx] = __float2bfloat16(res);
    }
}

// ---------------- 5. pack B (w_eff -> bf16 hi/lo, [tap][n][c]) ----------------
__global__ void pack_kernel() {
    int i = blockIdx.x * 256 + threadIdx.x;
    if (i >= TAPS * NOUT * NFEAT) return;
    int t = i / (NOUT * NFEAT);
    int rem = i % (NOUT * NFEAT);
    int n = rem / NFEAT, c = rem % NFEAT;
    float v = g_weff[(size_t)(c * 9 + t) * NOUTP + n];
    __nv_bfloat16 hi = __float2bfloat16(v);
    g_Bhi[(t * 64 + n) * NFEAT + c] = hi;
    g_Blo[(t * 64 + n) * NFEAT + c] = __float2bfloat16(v - __bfloat162float(hi));
}

// ---------------- 6. implicit-GEMM conv via mma.sync (bf16x3) ----------------
// grid 338, 256 threads (8 warps: 4 along M x 2 along N), dyn smem 110592
__global__ __launch_bounds__(256, 1) void gemm_kernel(float* __restrict__ out) {
    extern __shared__ __align__(128) char smem[];
    uint32_t sb = smem_u32(smem);
    int tid = threadIdx.x;
    int wid = tid >> 5, lane = tid & 31;
    int P0 = blockIdx.x * MTILE;
    int m_off = (wid & 3) * 32, n_off = (wid >> 2) * 32;
    int mi = lane >> 3, rr = lane & 7;
    int aRow = m_off + (mi & 1) * 8 + rr;
    int aCol = (mi >> 1) * 8;
    int bRow = n_off + (mi >> 1) * 8 + rr;
    int bCol = (mi & 1) * 8;

    float d[2][4][4];
#pragma unroll
    for (int mt = 0; mt < 2; mt++)
#pragma unroll
        for (int nt = 0; nt < 4; nt++)
#pragma unroll
            for (int i = 0; i < 4; i++) d[mt][nt][i] = 0.f;

    auto load_chunk = [&](int c, int st) {
        int tap = c >> 3, kc = c & 7;
        int dy = tap / 3 - 1, dx = tap % 3 - 1;
        long rowbase = (long)P0 + dy * PADW + dx + GUARD;
        int ch0 = kc * 64;
        uint32_t s = sb + st * STAGE;
#pragma unroll
        for (int q = tid; q < 1024; q += 256) {
            int row = q >> 3, cb = q & 7;
            uint32_t off = (uint32_t)(row * ASTR + cb * 8) * 2;
            size_t src = (size_t)(rowbase + row) * NFEAT + ch0 + cb * 8;
            cpa16(s + off,        &g_Ahi[src]);
            cpa16(s + A_LO + off, &g_Alo[src]);
        }
#pragma unroll
        for (int q = tid; q < 512; q += 256) {
            int row = q >> 3, cb = q & 7;
            uint32_t off = (uint32_t)(row * ASTR + cb * 8) * 2;
            size_t src = (size_t)(tap * 64 + row) * NFEAT + ch0 + cb * 8;
            cpa16(s + B_HI + off, &g_Bhi[src]);
            cpa16(s + B_LO + off, &g_Blo[src]);
        }
    };

    load_chunk(0, 0);
    CP_COMMIT();

    for (int c = 0; c < CHUNKS; c++) {
        if (c + 1 < CHUNKS) {
            load_chunk(c + 1, (c + 1) & 1);
            CP_COMMIT();
            CP_WAIT1();
        } else {
            CP_WAIT0();
        }
        __syncthreads();
        uint32_t s = sb + (c & 1) * STAGE;
#pragma unroll
        for (int ks = 0; ks < 4; ks++) {
            uint32_t ah[2][4], al[2][4], bh[2][4], bl[2][4];
#pragma unroll
            for (int mt = 0; mt < 2; mt++) {
                uint32_t off = (uint32_t)((aRow + mt * 16) * ASTR + ks * 16 + aCol) * 2;
                ldm4(ah[mt], s + off);
                ldm4(al[mt], s + A_LO + off);
            }
#pragma unroll
            for (int np = 0; np < 2; np++) {
                uint32_t off = (uint32_t)((bRow + np * 16) * ASTR + ks * 16 + bCol) * 2;
                ldm4(bh[np], s + B_HI + off);
                ldm4(bl[np], s + B_LO + off);
            }
#pragma unroll
            for (int mt = 0; mt < 2; mt++)
#pragma unroll
                for (int np = 0; np < 2; np++)
#pragma unroll
                    for (int hh = 0; hh < 2; hh++) {
                        int nt = np * 2 + hh;
                        mma16816(d[mt][nt], ah[mt], bh[np][hh * 2], bh[np][hh * 2 + 1]);
                        mma16816(d[mt][nt], ah[mt], bl[np][hh * 2], bl[np][hh * 2 + 1]);
                        mma16816(d[mt][nt], al[mt], bh[np][hh * 2], bh[np][hh * 2 + 1]);
                    }
        }
        __syncthreads();
    }

    // ---- store accumulators to smem (stride 66 f32), then per-pixel tail ----
    float* so = (float*)smem;
    int g = lane >> 2, t4 = lane & 3;
#pragma unroll
    for (int mt = 0; mt < 2; mt++)
#pragma unroll
        for (int nt = 0; nt < 4; nt++) {
            int row = m_off + mt * 16 + g;
            int col = n_off + nt * 8 + t4 * 2;
            *(float2*)&so[row * 66 + col]       = make_float2(d[mt][nt][0], d[mt][nt][1]);
            *(float2*)&so[(row + 8) * 66 + col] = make_float2(d[mt][nt][2], d[mt][nt][3]);
        }
    __syncthreads();

    if (tid < MTILE) {
        int P = P0 + tid;
        int b = P / PPB;
        int r = P % PPB;
        int ph_ = r / PADW, pw = r % PADW;
        if (ph_ >= 1 && ph_ <= 50 && pw >= 1 && pw <= 50) {
            int h = ph_ - 1, w = pw - 1;
            float acc[NOUT];
#pragma unroll
            for (int i = 0; i < NOUT; i++) acc[i] = so[tid * 66 + i] + g_beff[i];
            int n = h * (OUTW * AANCH) + w * AANCH;
            size_t bn = (size_t)b * NANCH;
#pragma unroll
            for (int a = 0; a < AANCH; a++) g_logits[bn + n + a] = acc[a];
#pragma unroll
            for (int a = 0; a < AANCH; a++) {
                float o0 = acc[9 + a * 4 + 0], o1 = acc[9 + a * 4 + 1];
                float o2 = acc[9 + a * 4 + 2], o3 = acc[9 + a * 4 + 3];
                size_t base = (bn + n + a) * 4;
                g_pred[base + 0] = o0; g_pred[base + 1] = o1;
                g_pred[base + 2] = o2; g_pred[base + 3] = o3;
                float x1, y1, x2, y2;
                anchor_box(h, w, a, x1, y1, x2, y2);
                float acx = (x1 + x2) * 0.5f, acy = (y1 + y2) * 0.5f;
                float aw = fmaxf(x2 - x1, 1e-6f), ah = fmaxf(y2 - y1, 1e-6f);
                float pcx = acx + o0 * aw, pcy = acy + o1 * ah;
                float pwid = aw * expf(o2), phei = ah * expf(o3);
                out[1 + base + 0] = pcx - pwid * 0.5f;
                out[1 + base + 1] = pcy - phei * 0.5f;
                out[1 + base + 2] = pcx + pwid * 0.5f;
                out[1 + base + 3] = pcy + phei * 0.5f;
            }
        }
    }
}

// ---------------- 7. IoU + per-gt max ----------------
__global__ void iou_kernel(const float* __restrict__ gt) {
    int b = blockIdx.y;
    int n = blockIdx.x * 256 + threadIdx.x;
    __shared__ float gx1[MGT], gy1[MGT], gx2[MGT], gy2[MGT];
    if (threadIdx.x < MGT) {
        int m = threadIdx.x;
        gx1[m] = gt[(b * MGT + m) * 4 + 0] * (1.f / 16.f);
        gy1[m] = gt[(b * MGT + m) * 4 + 1] * (1.f / 16.f);
        gx2[m] = gt[(b * MGT + m) * 4 + 2] * (1.f / 16.f);
        gy2[m] = gt[(b * MGT + m) * 4 + 3] * (1.f / 16.f);
    }
    __syncthreads();
    float lmax[MGT];
#pragma unroll
    for (int m = 0; m < MGT; m++) lmax[m] = 0.f;
    if (n < NANCH) {
        int h = n / (OUTW * AANCH);
        int rem = n % (OUTW * AANCH);
        int w = rem / AANCH, a = rem % AANCH;
        float x1, y1, x2, y2;
        anchor_box(h, w, a, x1, y1, x2, y2);
        float area_a = (x2 - x1) * (y2 - y1);
        size_t base = ((size_t)b * NANCH + n) * MGT;
#pragma unroll
        for (int m = 0; m < MGT; m++) {
            float ix1 = fmaxf(x1, gx1[m]), iy1 = fmaxf(y1, gy1[m]);
            float ix2 = fminf(x2, gx2[m]), iy2 = fminf(y2, gy2[m]);
            float inter = fmaxf(ix2 - ix1, 0.f) * fmaxf(iy2 - iy1, 0.f);
            float area_g = (gx2[m] - gx1[m]) * (gy2[m] - gy1[m]);
            float iou = inter / (area_a + area_g - inter + 1e-8f);
            g_iou[base + m] = iou;
            lmax[m] = iou;
        }
    }
#pragma unroll
    for (int m = 0; m < MGT; m++) {
#pragma unroll
        for (int s = 16; s; s >>= 1)
            lmax[m] = fmaxf(lmax[m], __shfl_xor_sync(0xffffffffu, lmax[m], s));
    }
    if ((threadIdx.x & 31) == 0) {
#pragma unroll
        for (int m = 0; m < MGT; m++)
            atomicMax((int*)&g_maxg[b * MGT + m], __float_as_int(lmax[m]));
    }
}

// ---------------- 8. loss ----------------
__global__ void loss_kernel(const float* __restrict__ gt) {
    int b = blockIdx.y;
    int n = blockIdx.x * 256 + threadIdx.x;
    __shared__ float gcx[MGT], gcy[MGT], gww[MGT], ghh[MGT], gmax[MGT];
    if (threadIdx.x < MGT) {
        int m = threadIdx.x;
        float x1 = gt[(b * MGT + m) * 4 + 0] * (1.f / 16.f);
        float y1 = gt[(b * MGT + m) * 4 + 1] * (1.f / 16.f);
        float x2 = gt[(b * MGT + m) * 4 + 2] * (1.f / 16.f);
        float y2 = gt[(b * MGT + m) * 4 + 3] * (1.f / 16.f);
        gcx[m] = (x1 + x2) * 0.5f;
        gcy[m] = (y1 + y2) * 0.5f;
        gww[m] = fmaxf(x2 - x1, 1e-6f);
        ghh[m] = fmaxf(y2 - y1, 1e-6f);
        gmax[m] = g_maxg[b * MGT + m];
    }
    __syncthreads();
    float cnt = 0.f, reg = 0.f, pls = 0.f, negcnt = 0.f, negls = 0.f;
    if (n < NANCH) {
        int h = n / (OUTW * AANCH);
        int rem = n % (OUTW * AANCH);
        int w = rem / AANCH, a = rem % AANCH;
        float x1, y1, x2, y2;
        anchor_box(h, w, a, x1, y1, x2, y2);
        float acx = (x1 + x2) * 0.5f, acy = (y1 + y2) * 0.5f;
        float aw = fmaxf(x2 - x1, 1e-6f), ah = fmaxf(y2 - y1, 1e-6f);
        float logit = g_logits[(size_t)b * NANCH + n];
        float sp_neg = softplusf(-logit);
        const float* pr = &g_pred[((size_t)b * NANCH + n) * 4];
        float p0 = pr[0], p1 = pr[1], p2 = pr[2], p3 = pr[3];
        size_t base = ((size_t)b * NANCH + n) * MGT;
        bool allneg = true;
#pragma unroll
        for (int m = 0; m < MGT; m++) {
            float iou = g_iou[base + m];
            bool pos = ((iou == gmax[m]) && (gmax[m] > 0.f)) || (iou > 0.7f);
            if (iou >= 0.3f) allneg = false;
            if (pos) {
                cnt += 1.f;
                float tx = (gcx[m] - acx) / aw;
                float ty = (gcy[m] - acy) / ah;
                float tw = logf(gww[m] / aw);
                float th = logf(ghh[m] / ah);
                reg += sl1(tx - p0) + sl1(ty - p1) + sl1(tw - p2) + sl1(th - p3);
                pls += sp_neg;
            }
        }
        if (allneg) { negcnt = 1.f; negls = softplusf(logit); }
    }
#pragma unroll
    for (int s = 16; s; s >>= 1) {
        cnt    += __shfl_xor_sync(0xffffffffu, cnt, s);
        reg    += __shfl_xor_sync(0xffffffffu, reg, s);
        pls    += __shfl_xor_sync(0xffffffffu, pls, s);
        negcnt += __shfl_xor_sync(0xffffffffu, negcnt, s);
        negls  += __shfl_xor_sync(0xffffffffu, negls, s);
    }
    if ((threadIdx.x & 31) == 0) {
        atomicAdd(&g_sums[0], cnt);
        atomicAdd(&g_sums[1], reg);
        atomicAdd(&g_sums[2], pls);
        atomicAdd(&g_sums[3], negcnt);
        atomicAdd(&g_sums[4], negls);
    }
}

// ---------------- 9. finalize ----------------
__global__ void fin_kernel(float* __restrict__ out) {
    float npos = fmaxf(g_sums[0], 1.f);
    float nneg = fmaxf(g_sums[3], 1.f);
    float reg_loss = g_sums[1] / (4.f * npos);
    float pos_loss = g_sums[2] / npos;
    float neg_loss = g_sums[4] / nneg;
    out[0] = 0.5f * (pos_loss + neg_loss) + 5.f * reg_loss;
}

// ---------------- launch ----------------
extern "C" void kernel_launch(void* const* d_in, const int* in_sizes, int n_in,
                              void* d_out, int out_size) {
    const float* feat = (const float*)d_in[0];
    const float* gt   = (const float*)d_in[1];
    const float* w1   = (const float*)d_in[2];
    const float* b1   = (const float*)d_in[3];
    const float* wcls = (const float*)d_in[4];
    const float* bcls = (const float*)d_in[5];
    const float* wbox = (const float*)d_in[6];
    const float* bbox = (const float*)d_in[7];
    float* out = (float*)d_out;

    cudaFuncSetAttribute(gemm_kernel, cudaFuncAttributeMaxDynamicSharedMemorySize, SMEM_TOTAL);

    init_kernel<<<(KCOLS * NOUTP + 255) / 256, 256>>>();
    compose_kernel<<<dim3(KCOLS / 128, NFEAT / CPCHUNK), 128>>>(w1, wcls, wbox);
    beff_kernel<<<1, 64>>>(b1, wcls, bcls, wbox, bbox);
    transpose_kernel<<<dim3(OUTW, BATCH, NFEAT / 64), 256>>>(feat);
    pack_kernel<<<(TAPS * NOUT * NFEAT + 255) / 256, 256>>>();
    gemm_kernel<<<NTILES, 256, SMEM_TOTAL>>>(out);
    iou_kernel<<<dim3((NANCH + 255) / 256, BATCH), 256>>>(gt);
    loss_kernel<<<dim3((NANCH + 255) / 256, BATCH), 256>>>(gt);
    fin_kernel<<<1, 1>>>(out);
}

// round 6
// speedup vs baseline: 2.7238x; 2.0467x over previous
#include <cuda_runtime.h>
#include <cuda_fp16.h>
#include <math.h>
#include <stdint.h>

#define OUTW  50
#define AANCH 9
#define NANCH 22500
#define BATCH 16
#define MGT   16
#define NFEAT 512
#define NOUT  45
#define NOUTP 48
#define KCOLS 4608
#define PADW  52
#define PPB   2704            // 52*52
#define MROWS 43264           // 16*2704
#define GUARD 64
#define AROWS (MROWS + 2*GUARD)
#define MTILE 128
#define NTILES 338            // 43264/128
#define TAPS  9
#define CHUNKS 72             // 9 taps * 8 ch-chunks of 64

// smem stage layout (fp16, row stride 72 elems = 144B -> conflict-free ldmatrix)
#define ASTR  72
#define B_OFF 18432           // 128*72*2
#define STAGE 27648           // + 64*72*2
#define SMEM_TOTAL (2*STAGE)  // 55296 (epilogue needs 128*66*4=33792, fits)

// ---------------- scratch ----------------
__device__ float g_weff[KCOLS * NOUTP];
__device__ float g_beff[NOUTP];
__device__ float g_logits[BATCH * NANCH];
__device__ float g_pred[(size_t)BATCH * NANCH * 4];
__device__ float g_iou[(size_t)BATCH * NANCH * MGT];
__device__ float g_maxg[BATCH * MGT];
__device__ float g_sums[8];
__device__ __half g_A[(size_t)AROWS * NFEAT];   // zero .bss: border/guard stay 0
__device__ __half g_B[TAPS * 64 * NFEAT];       // rows 45..63 stay 0

// ---------------- ptx helpers (baseline sm_80+ only) ----------------
__device__ __forceinline__ uint32_t smem_u32(const void* p) {
    uint32_t a;
    asm("{ .reg .u64 t; cvta.to.shared.u64 t, %1; cvt.u32.u64 %0, t; }" : "=r"(a) : "l"(p));
    return a;
}
__device__ __forceinline__ void cpa16(uint32_t dst, const void* src) {
    unsigned long long g = (unsigned long long)__cvta_generic_to_global(src);
    asm volatile("cp.async.cg.shared.global [%0], [%1], 16;" :: "r"(dst), "l"(g) : "memory");
}
#define CP_COMMIT() asm volatile("cp.async.commit_group;" ::: "memory")
#define CP_WAIT1()  asm volatile("cp.async.wait_group 1;" ::: "memory")
#define CP_WAIT0()  asm volatile("cp.async.wait_group 0;" ::: "memory")

__device__ __forceinline__ void ldm4(uint32_t* r, uint32_t addr) {
    asm volatile("ldmatrix.sync.aligned.m8n8.x4.shared.b16 {%0,%1,%2,%3}, [%4];"
                 : "=r"(r[0]), "=r"(r[1]), "=r"(r[2]), "=r"(r[3]) : "r"(addr));
}
__device__ __forceinline__ void mma16816(float* d, const uint32_t* a, uint32_t b0, uint32_t b1) {
    asm volatile("mma.sync.aligned.m16n8k16.row.col.f32.f16.f16.f32 "
                 "{%0,%1,%2,%3},{%4,%5,%6,%7},{%8,%9},{%0,%1,%2,%3};"
                 : "+f"(d[0]), "+f"(d[1]), "+f"(d[2]), "+f"(d[3])
                 : "r"(a[0]), "r"(a[1]), "r"(a[2]), "r"(a[3]), "r"(b0), "r"(b1));
}

// ---------------- math helpers ----------------
__device__ __forceinline__ void anchor_box(int h, int w, int a,
                                           float& x1, float& y1, float& x2, float& y2) {
    const float SC[3] = {2.f, 4.f, 6.f};
    const float RT[3] = {0.5f, 1.f, 1.5f};
    float s = SC[a % 3], r = RT[a / 3];
    float hw = s * r * 0.5f, hh = s * 0.5f;
    float cx = (float)h + 0.5f, cy = (float)w + 0.5f;
    x1 = fminf(fmaxf(cx - hw, 0.f), 50.f);
    x2 = fminf(fmaxf(cx + hw, 0.f), 50.f);
    y1 = fminf(fmaxf(cy - hh, 0.f), 50.f);
    y2 = fminf(fmaxf(cy + hh, 0.f), 50.f);
}
__device__ __forceinline__ float softplusf(float x) {
    return fmaxf(x, 0.f) + log1pf(expf(-fabsf(x)));
}
__device__ __forceinline__ float sl1(float d) {
    float ad = fabsf(d);
    return ad < 1.f ? 0.5f * d * d : ad - 0.5f;
}

// ---------------- 1. init (+ fused b_eff: depends only on inputs) ----------------
__global__ void init_kernel(const float* __restrict__ b1, const float* __restrict__ wcls,
                            const float* __restrict__ bcls, const float* __restrict__ wbox,
                            const float* __restrict__ bbox) {
    int i = blockIdx.x * 256 + threadIdx.x;
    if (i < KCOLS * NOUTP) g_weff[i] = 0.f;
    if (i < BATCH * MGT)   g_maxg[i] = 0.f;
    if (i < 8)             g_sums[i] = 0.f;
    if (blockIdx.x == 0 && threadIdx.x >= 192 && threadIdx.x < 192 + NOUTP) {
        int o = threadIdx.x - 192;
        if (o >= NOUT) { g_beff[o] = 0.f; return; }
        float s = (o < 9) ? bcls[o] : bbox[o - 9];
        const float* pr = (o < 9) ? &wcls[o * NFEAT] : &wbox[(o - 9) * NFEAT];
#pragma unroll 8
        for (int c = 0; c < NFEAT; c++) s += pr[c] * b1[c];
        g_beff[o] = s;
    }
}

// ---------------- 2. compose w_eff = proj @ w1 ----------------
#define CPCHUNK 64
__global__ __launch_bounds__(128) void compose_kernel(const float* __restrict__ w1,
                                                      const float* __restrict__ wcls,
                                                      const float* __restrict__ wbox) {
    __shared__ __align__(16) float projT[CPCHUNK][NOUTP];
    int cp0 = blockIdx.y * CPCHUNK;
    for (int i = threadIdx.x; i < CPCHUNK * NOUTP; i += 128) {
        int cp = i / NOUTP, o = i % NOUTP;
        float v = 0.f;
        if (o < 9)       v = wcls[o * NFEAT + cp0 + cp];
        else if (o < 45) v = wbox[(o - 9) * NFEAT + cp0 + cp];
        projT[cp][o] = v;
    }
    __syncthreads();
    int col = blockIdx.x * 128 + threadIdx.x;
    float acc[NOUTP];
#pragma unroll
    for (int o = 0; o < NOUTP; o++) acc[o] = 0.f;
#pragma unroll 4
    for (int cp = 0; cp < CPCHUNK; cp++) {
        float wv = w1[(size_t)(cp0 + cp) * KCOLS + col];
#pragma unroll
        for (int og = 0; og < 12; og++) {
            float4 pv = *(const float4*)&projT[cp][og * 4];
            acc[og * 4 + 0] += pv.x * wv;
            acc[og * 4 + 1] += pv.y * wv;
            acc[og * 4 + 2] += pv.z * wv;
            acc[og * 4 + 3] += pv.w * wv;
        }
    }
    float* dst = &g_weff[(size_t)col * NOUTP];
#pragma unroll
    for (int o = 0; o < NOUTP; o++) atomicAdd(&dst[o], acc[o]);
}

// ---------------- 3. transpose + fp16 (z<8), fused pack (z==8) ----------------
// grid (50, 16, 9), 256 threads. Stream order guarantees compose finished.
__global__ __launch_bounds__(256) void transpose_kernel(const float* __restrict__ feat) {
    if (blockIdx.z == 8) {
        // pack B: w_eff -> fp16 [tap][n][c]
        int bid = blockIdx.x * BATCH + blockIdx.y;       // 0..799
        for (int i = bid * 256 + threadIdx.x; i < TAPS * NOUT * NFEAT; i += 800 * 256) {
            int t = i / (NOUT * NFEAT);
            int rem = i % (NOUT * NFEAT);
            int n = rem / NFEAT, c = rem % NFEAT;
            g_B[(t * 64 + n) * NFEAT + c] = __float2half(g_weff[(size_t)(c * 9 + t) * NOUTP + n]);
        }
        return;
    }
    __shared__ float t[64][51];
    int h = blockIdx.x, b = blockIdx.y, c0 = blockIdx.z * 64;
    for (int i = threadIdx.x; i < 64 * 50; i += 256) {
        int c = i / 50, w = i % 50;
        t[c][w] = feat[(((size_t)b * NFEAT + c0 + c) * OUTW + h) * OUTW + w];
    }
    __syncthreads();
    for (int j = threadIdx.x; j < 64 * 50; j += 256) {
        int w = j >> 6, c = j & 63;
        size_t idx = ((size_t)(b * PPB + (h + 1) * PADW + (w + 1) + GUARD)) * NFEAT + c0 + c;
        g_A[idx] = __float2half(t[c][w]);
    }
}

// ---------------- 4. implicit-GEMM conv via fp16 mma.sync ----------------
// grid 338, 256 threads (8 warps: 4 along M x 2 along N), dyn smem 55296
__global__ __launch_bounds__(256) void gemm_kernel(float* __restrict__ out) {
    extern __shared__ __align__(128) char smem[];
    uint32_t sb = smem_u32(smem);
    int tid = threadIdx.x;
    int wid = tid >> 5, lane = tid & 31;
    int P0 = blockIdx.x * MTILE;
    int m_off = (wid & 3) * 32, n_off = (wid >> 2) * 32;
    int mi = lane >> 3, rr = lane & 7;
    int aRow = m_off + (mi & 1) * 8 + rr;
    int aCol = (mi >> 1) * 8;
    int bRow = n_off + (mi >> 1) * 8 + rr;
    int bCol = (mi & 1) * 8;

    float d[2][4][4];
#pragma unroll
    for (int mt = 0; mt < 2; mt++)
#pragma unroll
        for (int nt = 0; nt < 4; nt++)
#pragma unroll
            for (int i = 0; i < 4; i++) d[mt][nt][i] = 0.f;

    auto load_chunk = [&](int c, int st) {
        int tap = c >> 3, kc = c & 7;
        int dy = tap / 3 - 1, dx = tap % 3 - 1;
        long rowbase = (long)P0 + dy * PADW + dx + GUARD;
        int ch0 = kc * 64;
        uint32_t s = sb + st * STAGE;
#pragma unroll
        for (int q = tid; q < 1024; q += 256) {
            int row = q >> 3, cb = q & 7;
            uint32_t off = (uint32_t)(row * ASTR + cb * 8) * 2;
            cpa16(s + off, &g_A[(size_t)(rowbase + row) * NFEAT + ch0 + cb * 8]);
        }
#pragma unroll
        for (int q = tid; q < 512; q += 256) {
            int row = q >> 3, cb = q & 7;
            uint32_t off = (uint32_t)(row * ASTR + cb * 8) * 2;
            cpa16(s + B_OFF + off, &g_B[(size_t)(tap * 64 + row) * NFEAT + ch0 + cb * 8]);
        }
    };

    load_chunk(0, 0);
    CP_COMMIT();

    for (int c = 0; c < CHUNKS; c++) {
        if (c + 1 < CHUNKS) {
            load_chunk(c + 1, (c + 1) & 1);
            CP_COMMIT();
            CP_WAIT1();
        } else {
            CP_WAIT0();
        }
        __syncthreads();
        uint32_t s = sb + (c & 1) * STAGE;
#pragma unroll
        for (int ks = 0; ks < 4; ks++) {
            uint32_t a[2][4], bfr[2][4];
#pragma unroll
            for (int mt = 0; mt < 2; mt++) {
                uint32_t off = (uint32_t)((aRow + mt * 16) * ASTR + ks * 16 + aCol) * 2;
                ldm4(a[mt], s + off);
            }
#pragma unroll
            for (int np = 0; np < 2; np++) {
                uint32_t off = (uint32_t)((bRow + np * 16) * ASTR + ks * 16 + bCol) * 2;
                ldm4(bfr[np], s + B_OFF + off);
            }
#pragma unroll
            for (int mt = 0; mt < 2; mt++)
#pragma unroll
                for (int np = 0; np < 2; np++)
#pragma unroll
                    for (int hh = 0; hh < 2; hh++)
                        mma16816(d[mt][np * 2 + hh], a[mt], bfr[np][hh * 2], bfr[np][hh * 2 + 1]);
        }
        __syncthreads();
    }

    // ---- store accumulators to smem (stride 66 f32), then per-pixel tail ----
    float* so = (float*)smem;
    int g = lane >> 2, t4 = lane & 3;
#pragma unroll
    for (int mt = 0; mt < 2; mt++)
#pragma unroll
        for (int nt = 0; nt < 4; nt++) {
            int row = m_off + mt * 16 + g;
            int col = n_off + nt * 8 + t4 * 2;
            *(float2*)&so[row * 66 + col]       = make_float2(d[mt][nt][0], d[mt][nt][1]);
            *(float2*)&so[(row + 8) * 66 + col] = make_float2(d[mt][nt][2], d[mt][nt][3]);
        }
    __syncthreads();

    if (tid < MTILE) {
        int P = P0 + tid;
        int b = P / PPB;
        int r = P % PPB;
        int ph_ = r / PADW, pw = r % PADW;
        if (ph_ >= 1 && ph_ <= 50 && pw >= 1 && pw <= 50) {
            int h = ph_ - 1, w = pw - 1;
            float acc[NOUT];
#pragma unroll
            for (int i = 0; i < NOUT; i++) acc[i] = so[tid * 66 + i] + g_beff[i];
            int n = h * (OUTW * AANCH) + w * AANCH;
            size_t bn = (size_t)b * NANCH;
#pragma unroll
            for (int a = 0; a < AANCH; a++) g_logits[bn + n + a] = acc[a];
#pragma unroll
            for (int a = 0; a < AANCH; a++) {
                float o0 = acc[9 + a * 4 + 0], o1 = acc[9 + a * 4 + 1];
                float o2 = acc[9 + a * 4 + 2], o3 = acc[9 + a * 4 + 3];
                size_t base = (bn + n + a) * 4;
                g_pred[base + 0] = o0; g_pred[base + 1] = o1;
                g_pred[base + 2] = o2; g_pred[base + 3] = o3;
                float x1, y1, x2, y2;
                anchor_box(h, w, a, x1, y1, x2, y2);
                float acx = (x1 + x2) * 0.5f, acy = (y1 + y2) * 0.5f;
                float aw = fmaxf(x2 - x1, 1e-6f), ah = fmaxf(y2 - y1, 1e-6f);
                float pcx = acx + o0 * aw, pcy = acy + o1 * ah;
                float pwid = aw * expf(o2), phei = ah * expf(o3);
                out[1 + base + 0] = pcx - pwid * 0.5f;
                out[1 + base + 1] = pcy - phei * 0.5f;
                out[1 + base + 2] = pcx + pwid * 0.5f;
                out[1 + base + 3] = pcy + phei * 0.5f;
            }
        }
    }
}

// ---------------- 5. IoU + per-gt max ----------------
__global__ void iou_kernel(const float* __restrict__ gt) {
    int b = blockIdx.y;
    int n = blockIdx.x * 256 + threadIdx.x;
    __shared__ float gx1[MGT], gy1[MGT], gx2[MGT], gy2[MGT];
    if (threadIdx.x < MGT) {
        int m = threadIdx.x;
        gx1[m] = gt[(b * MGT + m) * 4 + 0] * (1.f / 16.f);
        gy1[m] = gt[(b * MGT + m) * 4 + 1] * (1.f / 16.f);
        gx2[m] = gt[(b * MGT + m) * 4 + 2] * (1.f / 16.f);
        gy2[m] = gt[(b * MGT + m) * 4 + 3] * (1.f / 16.f);
    }
    __syncthreads();
    float lmax[MGT];
#pragma unroll
    for (int m = 0; m < MGT; m++) lmax[m] = 0.f;
    if (n < NANCH) {
        int h = n / (OUTW * AANCH);
        int rem = n % (OUTW * AANCH);
        int w = rem / AANCH, a = rem % AANCH;
        float x1, y1, x2, y2;
        anchor_box(h, w, a, x1, y1, x2, y2);
        float area_a = (x2 - x1) * (y2 - y1);
        size_t base = ((size_t)b * NANCH + n) * MGT;
#pragma unroll
        for (int m = 0; m < MGT; m++) {
            float ix1 = fmaxf(x1, gx1[m]), iy1 = fmaxf(y1, gy1[m]);
            float ix2 = fminf(x2, gx2[m]), iy2 = fminf(y2, gy2[m]);
            float inter = fmaxf(ix2 - ix1, 0.f) * fmaxf(iy2 - iy1, 0.f);
            float area_g = (gx2[m] - gx1[m]) * (gy2[m] - gy1[m]);
            float iou = inter / (area_a + area_g - inter + 1e-8f);
            g_iou[base + m] = iou;
            lmax[m] = iou;
        }
    }
#pragma unroll
    for (int m = 0; m < MGT; m++) {
#pragma unroll
        for (int s = 16; s; s >>= 1)
            lmax[m] = fmaxf(lmax[m], __shfl_xor_sync(0xffffffffu, lmax[m], s));
    }
    if ((threadIdx.x & 31) == 0) {
#pragma unroll
        for (int m = 0; m < MGT; m++)
            atomicMax((int*)&g_maxg[b * MGT + m], __float_as_int(lmax[m]));
    }
}

// ---------------- 6. loss ----------------
__global__ void loss_kernel(const float* __restrict__ gt) {
    int b = blockIdx.y;
    int n = blockIdx.x * 256 + threadIdx.x;
    __shared__ float gcx[MGT], gcy[MGT], gww[MGT], ghh[MGT], gmax[MGT];
    if (threadIdx.x < MGT) {
        int m = threadIdx.x;
        float x1 = gt[(b * MGT + m) * 4 + 0] * (1.f / 16.f);
        float y1 = gt[(b * MGT + m) * 4 + 1] * (1.f / 16.f);
        float x2 = gt[(b * MGT + m) * 4 + 2] * (1.f / 16.f);
        float y2 = gt[(b * MGT + m) * 4 + 3] * (1.f / 16.f);
        gcx[m] = (x1 + x2) * 0.5f;
        gcy[m] = (y1 + y2) * 0.5f;
        gww[m] = fmaxf(x2 - x1, 1e-6f);
        ghh[m] = fmaxf(y2 - y1, 1e-6f);
        gmax[m] = g_maxg[b * MGT + m];
    }
    __syncthreads();
    float cnt = 0.f, reg = 0.f, pls = 0.f, negcnt = 0.f, negls = 0.f;
    if (n < NANCH) {
        int h = n / (OUTW * AANCH);
        int rem = n % (OUTW * AANCH);
        int w = rem / AANCH, a = rem % AANCH;
        float x1, y1, x2, y2;
        anchor_box(h, w, a, x1, y1, x2, y2);
        float acx = (x1 + x2) * 0.5f, acy = (y1 + y2) * 0.5f;
        float aw = fmaxf(x2 - x1, 1e-6f), ah = fmaxf(y2 - y1, 1e-6f);
        float logit = g_logits[(size_t)b * NANCH + n];
        float sp_neg = softplusf(-logit);
        const float* pr = &g_pred[((size_t)b * NANCH + n) * 4];
        float p0 = pr[0], p1 = pr[1], p2 = pr[2], p3 = pr[3];
        size_t base = ((size_t)b * NANCH + n) * MGT;
        bool allneg = true;
#pragma unroll
        for (int m = 0; m < MGT; m++) {
            float iou = g_iou[base + m];
            bool pos = ((iou == gmax[m]) && (gmax[m] > 0.f)) || (iou > 0.7f);
            if (iou >= 0.3f) allneg = false;
            if (pos) {
                cnt += 1.f;
                float tx = (gcx[m] - acx) / aw;
                float ty = (gcy[m] - acy) / ah;
                float tw = logf(gww[m] / aw);
                float th = logf(ghh[m] / ah);
                reg += sl1(tx - p0) + sl1(ty - p1) + sl1(tw - p2) + sl1(th - p3);
                pls += sp_neg;
            }
        }
        if (allneg) { negcnt = 1.f; negls = softplusf(logit); }
    }
#pragma unroll
    for (int s = 16; s; s >>= 1) {
        cnt    += __shfl_xor_sync(0xffffffffu, cnt, s);
        reg    += __shfl_xor_sync(0xffffffffu, reg, s);
        pls    += __shfl_xor_sync(0xffffffffu, pls, s);
        negcnt += __shfl_xor_sync(0xffffffffu, negcnt, s);
        negls  += __shfl_xor_sync(0xffffffffu, negls, s);
    }
    if ((threadIdx.x & 31) == 0) {
        atomicAdd(&g_sums[0], cnt);
        atomicAdd(&g_sums[1], reg);
        atomicAdd(&g_sums[2], pls);
        atomicAdd(&g_sums[3], negcnt);
        atomicAdd(&g_sums[4], negls);
    }
}

// ---------------- 7. finalize ----------------
__global__ void fin_kernel(float* __restrict__ out) {
    float npos = fmaxf(g_sums[0], 1.f);
    float nneg = fmaxf(g_sums[3], 1.f);
    float reg_loss = g_sums[1] / (4.f * npos);
    float pos_loss = g_sums[2] / npos;
    float neg_loss = g_sums[4] / nneg;
    out[0] = 0.5f * (pos_loss + neg_loss) + 5.f * reg_loss;
}

// ---------------- launch ----------------
extern "C" void kernel_launch(void* const* d_in, const int* in_sizes, int n_in,
                              void* d_out, int out_size) {
    const float* feat = (const float*)d_in[0];
    const float* gt   = (const float*)d_in[1];
    const float* w1   = (const float*)d_in[2];
    const float* b1   = (const float*)d_in[3];
    const float* wcls = (const float*)d_in[4];
    const float* bcls = (const float*)d_in[5];
    const float* wbox = (const float*)d_in[6];
    const float* bbox = (const float*)d_in[7];
    float* out = (float*)d_out;

    cudaFuncSetAttribute(gemm_kernel, cudaFuncAttributeMaxDynamicSharedMemorySize, SMEM_TOTAL);

    init_kernel<<<(KCOLS * NOUTP + 255) / 256, 256>>>(b1, wcls, bcls, wbox, bbox);
    compose_kernel<<<dim3(KCOLS / 128, NFEAT / CPCHUNK), 128>>>(w1, wcls, wbox);
    transpose_kernel<<<dim3(OUTW, BATCH, 9), 256>>>(feat);
    gemm_kernel<<<NTILES, 256, SMEM_TOTAL>>>(out);     // 4th launch -> ncu capture slot
    iou_kernel<<<dim3((NANCH + 255) / 256, BATCH), 256>>>(gt);
    loss_kernel<<<dim3((NANCH + 255) / 256, BATCH), 256>>>(gt);
    fin_kernel<<<1, 1>>>(out);
}